// round 9
// baseline (speedup 1.0000x reference)
#include <cuda_runtime.h>
#include <cuda_fp16.h>
#include <mma.h>
#include <cstdint>

using namespace nvcuda;

#define NT 20000
#define NC 80000
#define DIM 256
#define E_T2C 320000
#define E_C2T 320000
#define E_C2C 640000
#define E_T2T 160000

// ---------------- scratch (device globals; no allocations allowed) ----------
__device__ __half g_feat16[(size_t)(NT + NC) * DIM];       // [table | column]
__device__ __half g_W16[5 * DIM * DIM];                    // t2c,c2t,c2c,t2t,h
__device__ __half g_Wh_t2c[(size_t)NT * DIM];
__device__ __half g_Wh_c2t[(size_t)NC * DIM];
__device__ __half g_Wh_c2c[(size_t)NC * DIM];
__device__ __half g_Wh_t2t[(size_t)NT * DIM];
__device__ __half g_h16[(size_t)(NT + NC) * DIM];

#define CNT_T2C 0
#define CNT_C2T NC
#define CNT_C2C (NC + NT)
#define CNT_T2T (NC + NT + NC)
#define CNT_TOTAL (2 * NC + 2 * NT)
__device__ int g_cnt[CNT_TOTAL];
__device__ int g_off_t2c[NC + 1]; __device__ int g_pos_t2c[NC]; __device__ int g_e_t2c[E_T2C];
__device__ int g_off_c2t[NT + 1]; __device__ int g_pos_c2t[NT]; __device__ int g_e_c2t[E_C2T];
__device__ int g_off_c2c[NC + 1]; __device__ int g_pos_c2c[NC]; __device__ int g_e_c2c[E_C2C];
__device__ int g_off_t2t[NT + 1]; __device__ int g_pos_t2t[NT]; __device__ int g_e_t2t[E_T2T];

// scan partials: chunks per etype: NC->79, NT->20, NC->79, NT->20
#define NCH0 79
#define NCH1 20
#define NCH2 79
#define NCH3 20
#define NCH_TOTAL (NCH0 + NCH1 + NCH2 + NCH3)   // 198
__device__ int g_part[NCH_TOTAL];

// grid section sizes
#define GT_TILES 157            // (NT+127)/128
#define GC_TILES 625            // NC/128
#define GEMM_T_BLOCKS (GT_TILES * 4)
#define GEMM_C_BLOCKS (GC_TILES * 4)
#define BUILD_NB 592
#define MEGA_GEMM_BLOCKS (GEMM_T_BLOCKS + GEMM_C_BLOCKS + BUILD_NB)

#define CVT_FEAT_NB ((NT + NC) * DIM / 4 / 256)   // 25000
#define CVT_W_NB (5 * 16384 / 256)                // 320
#define HIST_NB 1184
#define MEGA1_BLOCKS (CVT_FEAT_NB + CVT_W_NB + HIST_NB)

// ---------------- helpers ----------------------------------------------------
__device__ __forceinline__ uint32_t smem_u32(const void* p) {
    uint32_t a;
    asm("{ .reg .u64 t; cvta.to.shared.u64 t, %1; cvt.u32.u64 %0, t; }" : "=r"(a) : "l"(p));
    return a;
}
#define CP_ASYNC16(dst, src) \
    asm volatile("cp.async.cg.shared.global [%0], [%1], 16;" :: "r"(dst), "l"(src))
#define CP_COMMIT() asm volatile("cp.async.commit_group;" ::: "memory")
#define CP_WAIT1() asm volatile("cp.async.wait_group 1;" ::: "memory")
#define CP_WAIT0() asm volatile("cp.async.wait_group 0;" ::: "memory")

__device__ __forceinline__ int warp_iscan(int v, int lane) {
    #pragma unroll
    for (int ofs = 1; ofs < 32; ofs <<= 1) {
        int t = __shfl_up_sync(0xffffffffu, v, ofs);
        if (lane >= ofs) v += t;
    }
    return v;
}

__device__ __forceinline__ void scan_map(int b, int& base, int& n, int& ch) {
    if (b < NCH0)                      { base = CNT_T2C; n = NC; ch = b; }
    else if (b < NCH0 + NCH1)          { base = CNT_C2T; n = NT; ch = b - NCH0; }
    else if (b < NCH0 + NCH1 + NCH2)   { base = CNT_C2C; n = NC; ch = b - NCH0 - NCH1; }
    else                               { base = CNT_T2T; n = NT; ch = b - NCH0 - NCH1 - NCH2; }
}

// ---------------- mega1: cvt_feat | cvt_w | hist ------------------------------
__global__ void mega1_kernel(const float* __restrict__ ft, const float* __restrict__ fc,
                             __half* __restrict__ feat16,
                             const float* __restrict__ w0, const float* __restrict__ w1,
                             const float* __restrict__ w2, const float* __restrict__ w3,
                             const float* __restrict__ w4, __half* __restrict__ W16,
                             const int* __restrict__ d0, const int* __restrict__ d1,
                             const int* __restrict__ d2, const int* __restrict__ d3,
                             int* __restrict__ cnt,
                             int E0, int E1, int E2, int E3) {
    const int bid = blockIdx.x, tid = threadIdx.x;
    if (bid < CVT_FEAT_NB) {
        int i = bid * 256 + tid;                 // float4 index
        const int n4T = NT * DIM / 4;
        float4 v = (i < n4T) ? ((const float4*)ft)[i] : ((const float4*)fc)[i - n4T];
        half2* dsp = (half2*)feat16;
        dsp[2 * i]     = __floats2half2_rn(v.x, v.y);
        dsp[2 * i + 1] = __floats2half2_rn(v.z, v.w);
        return;
    }
    if (bid < CVT_FEAT_NB + CVT_W_NB) {
        int i = (bid - CVT_FEAT_NB) * 256 + tid; // float4 index, 5*16384 total
        const float* srcs[5] = {w0, w1, w2, w3, w4};
        const float* s = srcs[i >> 14];
        float4 v = ((const float4*)s)[i & 16383];
        half2* dsp = (half2*)W16;
        dsp[2 * i]     = __floats2half2_rn(v.x, v.y);
        dsp[2 * i + 1] = __floats2half2_rn(v.z, v.w);
        return;
    }
    // hist section: grid-stride over all edges
    const int Eall = E0 + E1 + E2 + E3;
    int i = (bid - CVT_FEAT_NB - CVT_W_NB) * 256 + tid;
    const int stride = HIST_NB * 256;
    for (; i < Eall; i += stride) {
        int j = i;
        if (j < E0) { atomicAdd(&cnt[CNT_T2C + d0[j]], 1); continue; }
        j -= E0;
        if (j < E1) { atomicAdd(&cnt[CNT_C2T + d1[j]], 1); continue; }
        j -= E1;
        if (j < E2) { atomicAdd(&cnt[CNT_C2C + d2[j]], 1); continue; }
        j -= E2;
        atomicAdd(&cnt[CNT_T2T + d3[j]], 1);
    }
}

// ---------------- scan chain --------------------------------------------------
__global__ void scan_part_kernel(const int* __restrict__ cntbase, int* __restrict__ part) {
    int base, n, ch;
    scan_map(blockIdx.x, base, n, ch);
    const int tid = threadIdx.x, lane = tid & 31, warp = tid >> 5;
    int i = ch * 1024 + tid;
    int v = (i < n) ? cntbase[base + i] : 0;
    #pragma unroll
    for (int ofs = 16; ofs > 0; ofs >>= 1) v += __shfl_down_sync(0xffffffffu, v, ofs);
    __shared__ int ws[32];
    if (lane == 0) ws[warp] = v;
    __syncthreads();
    if (warp == 0) {
        int s = ws[lane];
        #pragma unroll
        for (int ofs = 16; ofs > 0; ofs >>= 1) s += __shfl_down_sync(0xffffffffu, s, ofs);
        if (lane == 0) part[blockIdx.x] = s;
    }
}

__global__ void scan_mid_kernel(int* __restrict__ part,
                                int* o0, int* o1, int* o2, int* o3) {
    __shared__ int sh[NCH_TOTAL];
    const int tid = threadIdx.x;
    for (int i = tid; i < NCH_TOTAL; i += blockDim.x) sh[i] = part[i];
    __syncthreads();
    if (tid == 0) {
        const int bnd[5] = {0, NCH0, NCH0 + NCH1, NCH0 + NCH1 + NCH2, NCH_TOTAL};
        int* offs[4] = {o0, o1, o2, o3};
        const int nlist[4] = {NC, NT, NC, NT};
        for (int e = 0; e < 4; e++) {
            int run = 0;
            for (int b = bnd[e]; b < bnd[e + 1]; b++) { int v = sh[b]; sh[b] = run; run += v; }
            offs[e][nlist[e]] = run;
        }
    }
    __syncthreads();
    for (int i = tid; i < NCH_TOTAL; i += blockDim.x) part[i] = sh[i];
}

__global__ void scan_out_kernel(const int* __restrict__ cntbase, const int* __restrict__ part,
                                int* o0, int* p0, int* o1, int* p1,
                                int* o2, int* p2, int* o3, int* p3) {
    int base, n, ch;
    scan_map(blockIdx.x, base, n, ch);
    int* off; int* pos;
    switch (base) {
        case CNT_T2C: off = o0; pos = p0; break;
        case CNT_C2T: off = o1; pos = p1; break;
        case CNT_C2C: off = o2; pos = p2; break;
        default:      off = o3; pos = p3; break;
    }
    const int tid = threadIdx.x, lane = tid & 31, warp = tid >> 5;
    int i = ch * 1024 + tid;
    int v = (i < n) ? cntbase[base + i] : 0;
    int incl = warp_iscan(v, lane);
    __shared__ int wpart[32];
    if (lane == 31) wpart[warp] = incl;
    __syncthreads();
    if (warp == 0) {
        int wv = wpart[lane];
        int ws = warp_iscan(wv, lane);
        wpart[lane] = ws - wv;
    }
    __syncthreads();
    int excl = part[blockIdx.x] + wpart[warp] + incl - v;
    if (i < n) { off[i] = excl; pos[i] = excl; }
}

// ---------------- fp16 GEMM core (KC=64, 2-stage cp.async) -------------------
#define AT_BYTES 18432
#define STG_BYTES 36864
#define GEMM_SMEM 73728

struct GemmCore {
    wmma::fragment<wmma::accumulator, 16, 16, 16, float> acc[2][4];
};

__device__ __forceinline__ void gemm_mainloop(
    const __half* __restrict__ A, const __half* __restrict__ W,
    char* smem, uint32_t sb, int bm, int M, int t, int wm, int wn,
    GemmCore& g) {
    #pragma unroll
    for (int i = 0; i < 2; i++)
        #pragma unroll
        for (int j = 0; j < 4; j++) wmma::fill_fragment(g.acc[i][j], 0.0f);

    auto prefetch = [&](int stage, int kb) {
        uint32_t baseA = sb + stage * STG_BYTES;
        uint32_t baseB = baseA + AT_BYTES;
        #pragma unroll
        for (int i = 0; i < 4; i++) {
            int idx = t + i * 256;
            int row = idx >> 3, seg = idx & 7;
            int grow = bm * 128 + row;
            if (grow > M - 1) grow = M - 1;
            CP_ASYNC16(baseA + (uint32_t)(row * 72 + seg * 8) * 2,
                       A + (size_t)grow * DIM + kb * 64 + seg * 8);
            CP_ASYNC16(baseB + (uint32_t)(row * 72 + seg * 8) * 2,
                       W + (size_t)row * DIM + kb * 64 + seg * 8);
        }
        CP_COMMIT();
    };

    prefetch(0, 0);

    for (int kb = 0; kb < 4; kb++) {
        const int s = kb & 1;
        if (kb < 3) { prefetch(s ^ 1, kb + 1); CP_WAIT1(); }
        else        { CP_WAIT0(); }
        __syncthreads();

        __half (*As)[72] = (__half(*)[72])(smem + s * STG_BYTES);
        __half (*Bs)[72] = (__half(*)[72])(smem + s * STG_BYTES + AT_BYTES);

        #pragma unroll
        for (int kk = 0; kk < 4; kk++) {
            wmma::fragment<wmma::matrix_a, 16, 16, 16, __half, wmma::row_major> a[2];
            wmma::fragment<wmma::matrix_b, 16, 16, 16, __half, wmma::col_major> b[4];
            #pragma unroll
            for (int i = 0; i < 2; i++)
                wmma::load_matrix_sync(a[i], &As[wm * 32 + i * 16][kk * 16], 72);
            #pragma unroll
            for (int j = 0; j < 4; j++)
                wmma::load_matrix_sync(b[j], &Bs[wn * 64 + j * 16][kk * 16], 72);
            #pragma unroll
            for (int i = 0; i < 2; i++)
                #pragma unroll
                for (int j = 0; j < 4; j++)
                    wmma::mma_sync(g.acc[i][j], a[i], b[j], g.acc[i][j]);
        }
        __syncthreads();
    }
}

// GEMM body with fp16 out (bias + lrelu), single-wave epilogue
__device__ __forceinline__ void gemm_body_h(
    const __half* __restrict__ A, const __half* __restrict__ W,
    const float* __restrict__ bias, __half* __restrict__ out,
    int M, int bm, int bn, char* smem, uint32_t sb, int t) {
    const int wid = t >> 5;
    const int wm = wid >> 1, wn = wid & 1;
    GemmCore g;
    gemm_mainloop(A, W + (size_t)bn * 128 * DIM, smem, sb, bm, M, t, wm, wn, g);

    float (*Cs)[132] = (float(*)[132])smem;       // 128x132 f4 = 67584 B
    #pragma unroll
    for (int i = 0; i < 2; i++)
        #pragma unroll
        for (int j = 0; j < 4; j++)
            wmma::store_matrix_sync(&Cs[wm * 32 + i * 16][wn * 64 + j * 16], g.acc[i][j],
                                    132, wmma::mem_row_major);
    __syncthreads();
    #pragma unroll
    for (int i = 0; i < 16; i++) {
        int idx = t + i * 256;            // 4096 float4
        int row = idx >> 5, c4 = idx & 31;
        int grow = bm * 128 + row;
        if (grow >= M) continue;
        int col = bn * 128 + c4 * 4;
        float4 v = *(float4*)&Cs[row][c4 * 4];
        float4 bb = *(const float4*)&bias[col];
        v.x += bb.x; v.y += bb.y; v.z += bb.z; v.w += bb.w;
        v.x = v.x >= 0.f ? v.x : 0.01f * v.x;
        v.y = v.y >= 0.f ? v.y : 0.01f * v.y;
        v.z = v.z >= 0.f ? v.z : 0.01f * v.z;
        v.w = v.w >= 0.f ? v.w : 0.01f * v.w;
        half2 h0 = __floats2half2_rn(v.x, v.y);
        half2 h1 = __floats2half2_rn(v.z, v.w);
        *(uint2*)&out[(size_t)grow * DIM + col] =
            make_uint2(*(uint32_t*)&h0, *(uint32_t*)&h1);
    }
}

// mega GEMM launch: [table dual GEMM | column dual GEMM | CSR build]
__global__ __launch_bounds__(256, 2)
void mega_gemm_build_kernel(
    const __half* __restrict__ featT, const __half* __restrict__ featC,
    const __half* __restrict__ W16,
    const float* __restrict__ b_t2c, const float* __restrict__ b_t2t,
    const float* __restrict__ b_c2t, const float* __restrict__ b_c2c,
    __half* __restrict__ Wh_t2c, __half* __restrict__ Wh_t2t,
    __half* __restrict__ Wh_c2t, __half* __restrict__ Wh_c2c,
    const int* __restrict__ s0, const int* __restrict__ d0, int* p0, int* e0,
    const int* __restrict__ s1, const int* __restrict__ d1, int* p1, int* e1,
    const int* __restrict__ s2, const int* __restrict__ d2, int* p2, int* e2,
    const int* __restrict__ s3, const int* __restrict__ d3, int* p3, int* e3,
    int E0, int E1, int E2, int E3) {
    extern __shared__ __align__(16) char smem[];
    const int t = threadIdx.x;
    int bid = blockIdx.x;

    if (bid < GEMM_T_BLOCKS) {
        const uint32_t sb = smem_u32(smem);
        int bm = bid >> 2, by = bid & 3;
        int which = by >> 1, bn = by & 1;
        const __half* W = W16 + (which ? 3 : 0) * DIM * DIM;   // t2c or t2t
        const float* bias = which ? b_t2t : b_t2c;
        __half* out = which ? Wh_t2t : Wh_t2c;
        gemm_body_h(featT, W, bias, out, NT, bm, bn, smem, sb, t);
        return;
    }
    bid -= GEMM_T_BLOCKS;
    if (bid < GEMM_C_BLOCKS) {
        const uint32_t sb = smem_u32(smem);
        int bm = bid >> 2, by = bid & 3;
        int which = by >> 1, bn = by & 1;
        const __half* W = W16 + (which ? 2 : 1) * DIM * DIM;   // c2t or c2c
        const float* bias = which ? b_c2c : b_c2t;
        __half* out = which ? Wh_c2c : Wh_c2t;
        gemm_body_h(featC, W, bias, out, NC, bm, bn, smem, sb, t);
        return;
    }
    bid -= GEMM_C_BLOCKS;
    // build section: grid-stride over all edges
    const int Eall = E0 + E1 + E2 + E3;
    int i = bid * 256 + t;
    const int stride = BUILD_NB * 256;
    for (; i < Eall; i += stride) {
        int j = i;
        if (j < E0) { int sl = atomicAdd(&p0[d0[j]], 1); e0[sl] = s0[j]; continue; }
        j -= E0;
        if (j < E1) { int sl = atomicAdd(&p1[d1[j]], 1); e1[sl] = s1[j]; continue; }
        j -= E1;
        if (j < E2) { int sl = atomicAdd(&p2[d2[j]], 1); e2[sl] = s2[j]; continue; }
        j -= E2;
        int sl = atomicAdd(&p3[d3[j]], 1); e3[sl] = s3[j];
    }
}

// final GEMM: +residual, fp32 out. grid (gAll, 2)
__global__ __launch_bounds__(256, 2)
void gemm_final_kernel(const __half* __restrict__ A, const __half* __restrict__ W,
                       const float* __restrict__ bias,
                       const float* __restrict__ resA, const float* __restrict__ resB,
                       int splitM, float* __restrict__ C, int M) {
    extern __shared__ __align__(16) char smem[];
    const int bm = blockIdx.x, bn = blockIdx.y;
    const int t = threadIdx.x;
    const int wid = t >> 5;
    const int wm = wid >> 1, wn = wid & 1;
    const uint32_t sb = smem_u32(smem);

    GemmCore g;
    gemm_mainloop(A, W + (size_t)bn * 128 * DIM, smem, sb, bm, M, t, wm, wn, g);

    float (*Cs)[132] = (float(*)[132])smem;
    #pragma unroll
    for (int i = 0; i < 2; i++)
        #pragma unroll
        for (int j = 0; j < 4; j++)
            wmma::store_matrix_sync(&Cs[wm * 32 + i * 16][wn * 64 + j * 16], g.acc[i][j],
                                    132, wmma::mem_row_major);
    __syncthreads();
    #pragma unroll
    for (int i = 0; i < 16; i++) {
        int idx = t + i * 256;
        int row = idx >> 5, c4 = idx & 31;
        int grow = bm * 128 + row;
        if (grow >= M) continue;
        int col = bn * 128 + c4 * 4;
        float4 v = *(float4*)&Cs[row][c4 * 4];
        float4 bb = *(const float4*)&bias[col];
        v.x += bb.x; v.y += bb.y; v.z += bb.z; v.w += bb.w;
        v.x = v.x >= 0.f ? v.x : 0.01f * v.x;
        v.y = v.y >= 0.f ? v.y : 0.01f * v.y;
        v.z = v.z >= 0.f ? v.z : 0.01f * v.z;
        v.w = v.w >= 0.f ? v.w : 0.01f * v.w;
        const float* rp = (grow < splitM)
            ? &resA[(size_t)grow * DIM + col]
            : &resB[(size_t)(grow - splitM) * DIM + col];
        float4 f = *(const float4*)rp;
        v.x += f.x; v.y += f.y; v.z += f.z; v.w += f.w;
        *(float4*)&C[(size_t)grow * DIM + col] = v;
    }
}

// ---------------- aggregation (both ntypes, one launch) ----------------------
__global__ void agg_all_kernel(
    const __half* __restrict__ Wh_c2t, const int* __restrict__ off_c2t, const int* __restrict__ e_c2t,
    const __half* __restrict__ Wh_t2t, const int* __restrict__ off_t2t, const int* __restrict__ e_t2t,
    const __half* __restrict__ Wh_t2c, const int* __restrict__ off_t2c, const int* __restrict__ e_t2c,
    const __half* __restrict__ Wh_c2c, const int* __restrict__ off_c2c, const int* __restrict__ e_c2c,
    __half* __restrict__ h) {
    int dg = blockIdx.x * 8 + (threadIdx.x >> 5);
    int c = threadIdx.x & 31;
    if (dg >= NT + NC) return;

    const __half* WhA; const int* offA; const int* eA;
    const __half* WhB; const int* offB; const int* eB;
    int d;
    if (dg < NT) {
        d = dg;
        WhA = Wh_c2t; offA = off_c2t; eA = e_c2t;
        WhB = Wh_t2t; offB = off_t2t; eB = e_t2t;
    } else {
        d = dg - NT;
        WhA = Wh_t2c; offA = off_t2c; eA = e_t2c;
        WhB = Wh_c2c; offB = off_c2c; eB = e_c2c;
    }

    const uint4* A4 = (const uint4*)WhA;
    const uint4* B4 = (const uint4*)WhB;

    float acc[8];
    #pragma unroll
    for (int k = 0; k < 8; k++) acc[k] = 0.f;

    auto addv = [&](uint4 v) {
        half2* hv = (half2*)&v;
        #pragma unroll
        for (int k = 0; k < 4; k++) {
            float2 f = __half22float2(hv[k]);
            acc[2 * k] += f.x; acc[2 * k + 1] += f.y;
        }
    };

    auto run = [&](const uint4* T4, const int* e, int s0, int s1) {
        int j = s0;
        for (; j + 3 < s1; j += 4) {
            int i0 = __ldg(&e[j]),     i1 = __ldg(&e[j + 1]);
            int i2 = __ldg(&e[j + 2]), i3 = __ldg(&e[j + 3]);
            uint4 v0 = __ldg(&T4[(size_t)i0 * 32 + c]);
            uint4 v1 = __ldg(&T4[(size_t)i1 * 32 + c]);
            uint4 v2 = __ldg(&T4[(size_t)i2 * 32 + c]);
            uint4 v3 = __ldg(&T4[(size_t)i3 * 32 + c]);
            addv(v0); addv(v1); addv(v2); addv(v3);
        }
        for (; j < s1; j++) addv(__ldg(&T4[(size_t)__ldg(&e[j]) * 32 + c]));
    };

    int s0 = offA[d], s1 = offA[d + 1];
    run(A4, eA, s0, s1);
    float invA = 0.5f / (float)max(s1 - s0, 1);
    float r[8];
    #pragma unroll
    for (int k = 0; k < 8; k++) { r[k] = acc[k] * invA; acc[k] = 0.f; }

    s0 = offB[d]; s1 = offB[d + 1];
    run(B4, eB, s0, s1);
    float invB = 0.5f / (float)max(s1 - s0, 1);
    #pragma unroll
    for (int k = 0; k < 8; k++) r[k] += acc[k] * invB;

    uint4 o;
    half2 p0 = __floats2half2_rn(r[0], r[1]);
    half2 p1 = __floats2half2_rn(r[2], r[3]);
    half2 p2 = __floats2half2_rn(r[4], r[5]);
    half2 p3 = __floats2half2_rn(r[6], r[7]);
    o.x = *(uint32_t*)&p0; o.y = *(uint32_t*)&p1;
    o.z = *(uint32_t*)&p2; o.w = *(uint32_t*)&p3;
    ((uint4*)h)[(size_t)dg * 32 + c] = o;
}

// ---------------- launch -----------------------------------------------------
extern "C" void kernel_launch(void* const* d_in, const int* in_sizes, int n_in,
                              void* d_out, int out_size) {
    const float* feat_table = (const float*)d_in[0];
    const float* feat_col   = (const float*)d_in[1];
    const float* W_t2c = (const float*)d_in[2];  const float* b_t2c = (const float*)d_in[3];
    const float* W_c2t = (const float*)d_in[4];  const float* b_c2t = (const float*)d_in[5];
    const float* W_c2c = (const float*)d_in[6];  const float* b_c2c = (const float*)d_in[7];
    const float* W_t2t = (const float*)d_in[8];  const float* b_t2t = (const float*)d_in[9];
    const float* W_h   = (const float*)d_in[10]; const float* b_h   = (const float*)d_in[11];
    const int* src_t2c = (const int*)d_in[12]; const int* dst_t2c = (const int*)d_in[13];
    const int* src_c2t = (const int*)d_in[14]; const int* dst_c2t = (const int*)d_in[15];
    const int* src_c2c = (const int*)d_in[16]; const int* dst_c2c = (const int*)d_in[17];
    const int* src_t2t = (const int*)d_in[18]; const int* dst_t2t = (const int*)d_in[19];
    float* out = (float*)d_out;

    __half *feat16, *W16, *Wh_t2c, *Wh_c2t, *Wh_c2c, *Wh_t2t, *h16;
    int *cnt, *part;
    int *off_t2c, *pos_t2c, *e_t2c;
    int *off_c2t, *pos_c2t, *e_c2t;
    int *off_c2c, *pos_c2c, *e_c2c;
    int *off_t2t, *pos_t2t, *e_t2t;
    cudaGetSymbolAddress((void**)&feat16, g_feat16);
    cudaGetSymbolAddress((void**)&W16, g_W16);
    cudaGetSymbolAddress((void**)&Wh_t2c, g_Wh_t2c);
    cudaGetSymbolAddress((void**)&Wh_c2t, g_Wh_c2t);
    cudaGetSymbolAddress((void**)&Wh_c2c, g_Wh_c2c);
    cudaGetSymbolAddress((void**)&Wh_t2t, g_Wh_t2t);
    cudaGetSymbolAddress((void**)&h16, g_h16);
    cudaGetSymbolAddress((void**)&cnt, g_cnt);
    cudaGetSymbolAddress((void**)&part, g_part);
    cudaGetSymbolAddress((void**)&off_t2c, g_off_t2c); cudaGetSymbolAddress((void**)&pos_t2c, g_pos_t2c);
    cudaGetSymbolAddress((void**)&e_t2c, g_e_t2c);
    cudaGetSymbolAddress((void**)&off_c2t, g_off_c2t); cudaGetSymbolAddress((void**)&pos_c2t, g_pos_c2t);
    cudaGetSymbolAddress((void**)&e_c2t, g_e_c2t);
    cudaGetSymbolAddress((void**)&off_c2c, g_off_c2c); cudaGetSymbolAddress((void**)&pos_c2c, g_pos_c2c);
    cudaGetSymbolAddress((void**)&e_c2c, g_e_c2c);
    cudaGetSymbolAddress((void**)&off_t2t, g_off_t2t); cudaGetSymbolAddress((void**)&pos_t2t, g_pos_t2t);
    cudaGetSymbolAddress((void**)&e_t2t, g_e_t2t);

    cudaFuncSetAttribute(mega_gemm_build_kernel, cudaFuncAttributeMaxDynamicSharedMemorySize, GEMM_SMEM);
    cudaFuncSetAttribute(gemm_final_kernel,      cudaFuncAttributeMaxDynamicSharedMemorySize, GEMM_SMEM);

    const int Et2c = in_sizes[12], Ec2t = in_sizes[14], Ec2c = in_sizes[16], Et2t = in_sizes[18];

    cudaMemsetAsync(cnt, 0, CNT_TOTAL * sizeof(int), 0);

    mega1_kernel<<<MEGA1_BLOCKS, 256>>>(feat_table, feat_col, feat16,
                                        W_t2c, W_c2t, W_c2c, W_t2t, W_h, W16,
                                        dst_t2c, dst_c2t, dst_c2c, dst_t2t, cnt,
                                        Et2c, Ec2t, Ec2c, Et2t);

    scan_part_kernel<<<NCH_TOTAL, 1024>>>(cnt, part);
    scan_mid_kernel<<<1, 256>>>(part, off_t2c, off_c2t, off_c2c, off_t2t);
    scan_out_kernel<<<NCH_TOTAL, 1024>>>(cnt, part,
                                         off_t2c, pos_t2c, off_c2t, pos_c2t,
                                         off_c2c, pos_c2c, off_t2t, pos_t2t);

    const __half* featT16 = feat16;
    const __half* featC16 = feat16 + (size_t)NT * DIM;

    mega_gemm_build_kernel<<<MEGA_GEMM_BLOCKS, 256, GEMM_SMEM>>>(
        featT16, featC16, W16,
        b_t2c, b_t2t, b_c2t, b_c2c,
        Wh_t2c, Wh_t2t, Wh_c2t, Wh_c2c,
        src_t2c, dst_t2c, pos_t2c, e_t2c,
        src_c2t, dst_c2t, pos_c2t, e_c2t,
        src_c2c, dst_c2c, pos_c2c, e_c2c,
        src_t2t, dst_t2t, pos_t2t, e_t2t,
        Et2c, Ec2t, Ec2c, Et2t);

    agg_all_kernel<<<(NT + NC + 7) / 8, 256>>>(
        Wh_c2t, off_c2t, e_c2t, Wh_t2t, off_t2t, e_t2t,
        Wh_t2c, off_t2c, e_t2c, Wh_c2c, off_c2c, e_c2c, h16);

    const int gAll = (NT + NC + 127) / 128;
    gemm_final_kernel<<<dim3(gAll, 2), 256, GEMM_SMEM>>>(
        h16, W16 + 4 * DIM * DIM, b_h, feat_table, feat_col, NT, out, NT + NC);
}